// round 8
// baseline (speedup 1.0000x reference)
#include <cuda_runtime.h>
#include <cuda_bf16.h>
#include <cstdint>

#define N_NODES 50000
#define N_EDGES 800000
#define HDIM    128
#define PAD     132
#define AS_FLOATS (64 * PAD)
#define BS_FLOATS (HDIM * HDIM)
#define SMEM_PROJ ((AS_FLOATS + BS_FLOATS) * 4)
#define SMEM_NODE ((2 * AS_FLOATS + BS_FLOATS) * 4)

// edge-HMMA tile config: 128 edges x 128 cols, bf16 hi/lo split in smem
#define TS   128
#define BPAD 136                                  // bf16 row stride (272B -> 4-bank shift/row)
#define TILE_BF (128 * BPAD)                      // elements per 128x128 tile
#define SMEM_EDGE_DYN (4 * TILE_BF * 2)           // Ahi|Alo|Whi|Wlo, bytes = 139264

// Scratch (device globals — no allocation allowed)
__device__ __align__(16) float g_P[N_NODES * 256];     // [Pa(+b1) | Pb] per node
__device__ __align__(16) float g_Hagg[N_NODES * HDIM]; // segment_sum of relu'd hidden
__device__ __align__(16) float g_deg[N_NODES];         // in-degree (float)
__device__ int g_idx_is64;                             // edge_index dtype flag

// ---------------------------------------------------------------------------
__device__ __forceinline__ void red4(float* p, float a, float b, float c, float d) {
    asm volatile("red.global.add.v4.f32 [%0], {%1,%2,%3,%4};"
                 :: "l"(p), "f"(a), "f"(b), "f"(c), "f"(d) : "memory");
}
__device__ __forceinline__ void red2(float* p, float a, float b) {
    asm volatile("red.global.add.v2.f32 [%0], {%1,%2};"
                 :: "l"(p), "f"(a), "f"(b) : "memory");
}
__device__ __forceinline__ void red1(float* p, float v) {
    asm volatile("red.global.add.f32 [%0], %1;" :: "l"(p), "f"(v) : "memory");
}

// m16n8k16 row.col bf16 -> f32 accumulate (HMMA fallback path, baseline PTX)
__device__ __forceinline__ void mma16816(float c[4], const uint32_t a[4],
                                         uint32_t b0, uint32_t b1) {
    asm volatile(
        "mma.sync.aligned.m16n8k16.row.col.f32.bf16.bf16.f32 "
        "{%0,%1,%2,%3}, {%4,%5,%6,%7}, {%8,%9}, {%0,%1,%2,%3};"
        : "+f"(c[0]), "+f"(c[1]), "+f"(c[2]), "+f"(c[3])
        : "r"(a[0]), "r"(a[1]), "r"(a[2]), "r"(a[3]), "r"(b0), "r"(b1));
}

__device__ __forceinline__ uint32_t pack_bf2(float v0, float v1, uint32_t& lo) {
    __nv_bfloat16 h0 = __float2bfloat16_rn(v0);
    __nv_bfloat16 h1 = __float2bfloat16_rn(v1);
    __nv_bfloat16 l0 = __float2bfloat16_rn(v0 - __bfloat162float(h0));
    __nv_bfloat16 l1 = __float2bfloat16_rn(v1 - __bfloat162float(h1));
    lo = (uint32_t)__bfloat16_as_ushort(l0) | ((uint32_t)__bfloat16_as_ushort(l1) << 16);
    return (uint32_t)__bfloat16_as_ushort(h0) | ((uint32_t)__bfloat16_as_ushort(h1) << 16);
}

// ---------------------------------------------------------------------------
// SIMT GEMM helpers (node kernels)
__device__ __forceinline__ void load_A(float* As, const float* __restrict__ src,
                                       int nrows, int tid) {
#pragma unroll
    for (int t = 0; t < 8; ++t) {
        int g  = tid + t * 256;
        int r  = g >> 5;
        int c4 = g & 31;
        float4 v = make_float4(0.f, 0.f, 0.f, 0.f);
        if (r < nrows) v = *(const float4*)(src + r * HDIM + c4 * 4);
        *(float4*)(As + r * PAD + c4 * 4) = v;
    }
}
__device__ __forceinline__ void load_B(float* Bs, const float* __restrict__ B, int tid) {
    const float4* s = (const float4*)B;
    float4* d = (float4*)Bs;
#pragma unroll
    for (int t = 0; t < 16; ++t) d[tid + t * 256] = s[tid + t * 256];
}
__device__ __forceinline__ void gemm_tile(const float* __restrict__ As,
                                          const float* __restrict__ Bs,
                                          float acc[4][8], int tx, int ty) {
    const int r0 = ty * 4, c0 = tx * 8;
#pragma unroll 2
    for (int kk = 0; kk < HDIM; kk += 4) {
        float a[4][4];
#pragma unroll
        for (int i = 0; i < 4; ++i)
            *(float4*)a[i] = *(const float4*)(As + (r0 + i) * PAD + kk);
#pragma unroll
        for (int u = 0; u < 4; ++u) {
            float b[8];
            *(float4*)&b[0] = *(const float4*)(Bs + (kk + u) * HDIM + c0);
            *(float4*)&b[4] = *(const float4*)(Bs + (kk + u) * HDIM + c0 + 4);
#pragma unroll
            for (int i = 0; i < 4; ++i)
#pragma unroll
                for (int j = 0; j < 8; ++j)
                    acc[i][j] = fmaf(a[i][u], b[j], acc[i][j]);
        }
    }
}
__device__ __forceinline__ void zero_acc(float acc[4][8]) {
#pragma unroll
    for (int i = 0; i < 4; ++i)
#pragma unroll
        for (int j = 0; j < 8; ++j) acc[i][j] = 0.f;
}

// ---------------------------------------------------------------------------
__global__ void k_detect(const long long* __restrict__ ei) {
    if (threadIdx.x == 0 && blockIdx.x == 0) {
        int ok = 1;
        for (int i = 0; i < 64; ++i) {
            long long v = ei[i];
            if (v < 0 || v >= N_NODES) { ok = 0; break; }
        }
        g_idx_is64 = ok;
    }
}

__global__ void k_zero() {
    int idx = blockIdx.x * blockDim.x + threadIdx.x;
    float4* p = (float4*)g_Hagg;
    const int n4 = N_NODES * HDIM / 4;
    for (int i = idx; i < n4; i += 256 * 256) p[i] = make_float4(0.f, 0.f, 0.f, 0.f);
    for (int i = idx; i < N_NODES; i += 256 * 256) g_deg[i] = 0.f;
}

// P = [x@W1a + b1 | x@W1b]
__global__ __launch_bounds__(256) void k_node_proj(const float* __restrict__ x,
                                                   const float* __restrict__ We1,
                                                   const float* __restrict__ be1) {
    extern __shared__ float smem[];
    float* As = smem;
    float* Bs = smem + AS_FLOATS;
    const int tid = threadIdx.x, tx = tid & 15, ty = tid >> 4;
    const int c0 = tx * 8, r0 = ty * 4;
    const int n0 = blockIdx.x * 64;
    const int nrows = min(64, N_NODES - n0);

    load_A(As, x + (size_t)n0 * HDIM, nrows, tid);
    load_B(Bs, We1, tid);
    __syncthreads();
    float acc[4][8]; zero_acc(acc);
    gemm_tile(As, Bs, acc, tx, ty);
    float4 b0 = *(const float4*)(be1 + c0);
    float4 b1 = *(const float4*)(be1 + c0 + 4);
#pragma unroll
    for (int i = 0; i < 4; ++i) {
        int r = r0 + i;
        if (r < nrows) {
            float* dst = g_P + (size_t)(n0 + r) * 256 + c0;
            *(float4*)dst       = make_float4(acc[i][0]+b0.x, acc[i][1]+b0.y, acc[i][2]+b0.z, acc[i][3]+b0.w);
            *(float4*)(dst + 4) = make_float4(acc[i][4]+b1.x, acc[i][5]+b1.y, acc[i][6]+b1.z, acc[i][7]+b1.w);
        }
    }
    __syncthreads();
    load_B(Bs, We1 + 128 * HDIM, tid);
    __syncthreads();
    zero_acc(acc);
    gemm_tile(As, Bs, acc, tx, ty);
#pragma unroll
    for (int i = 0; i < 4; ++i) {
        int r = r0 + i;
        if (r < nrows) {
            float* dst = g_P + (size_t)(n0 + r) * 256 + 128 + c0;
            *(float4*)dst       = make_float4(acc[i][0], acc[i][1], acc[i][2], acc[i][3]);
            *(float4*)(dst + 4) = make_float4(acc[i][4], acc[i][5], acc[i][6], acc[i][7]);
        }
    }
}

// ---------------------------------------------------------------------------
// HMMA edge kernel: h = relu(ea@W1c + Pa[row] + Pb[col]); scatter h, deg.
// ea@W1c via mma.sync bf16 3-pass hi/lo split, fp32 accumulate in registers.
// 8 warps as 4(m) x 2(n): warp owns 32 edges x 64 cols.
__global__ __launch_bounds__(256, 1) void k_edge_hmma(const float* __restrict__ edge_attr,
                                                      const void* __restrict__ edge_index,
                                                      const float* __restrict__ We1) {
    extern __shared__ __nv_bfloat16 sm[];
    __shared__ int rows_s[TS];
    __shared__ int cols_s[TS];

    const int tid = threadIdx.x, wid = tid >> 5, lane = tid & 31;
    const int g = lane >> 2, tg = lane & 3;
    __nv_bfloat16* Ahi = sm;
    __nv_bfloat16* Alo = sm + TILE_BF;
    __nv_bfloat16* Whi = sm + 2 * TILE_BF;
    __nv_bfloat16* Wlo = sm + 3 * TILE_BF;

    // Convert W1c^T -> Whi/Wlo [n][k] (once per CTA)
    {
        const float* W = We1 + 256 * HDIM;          // W1c rows of We1
        int n = tid >> 1, k0 = (tid & 1) * 64;
        for (int kk = 0; kk < 64; kk += 2) {
            float v0 = W[(k0 + kk) * HDIM + n];
            float v1 = W[(k0 + kk + 1) * HDIM + n];
            uint32_t lo, hi = pack_bf2(v0, v1, lo);
            *(uint32_t*)&Whi[n * BPAD + k0 + kk] = hi;
            *(uint32_t*)&Wlo[n * BPAD + k0 + kk] = lo;
        }
    }

    const int is64 = g_idx_is64;
    const long long* ei64 = (const long long*)edge_index;
    const int*       ei32 = (const int*)edge_index;

    const int m0 = (wid & 3) * 32;                  // edge-row base for this warp
    const int nb = (wid >> 2) * 64;                 // col base for this warp
    const int ntiles = N_EDGES / TS;                // 6250, no tail

    for (int t = blockIdx.x; t < ntiles; t += gridDim.x) {
        const long long e0 = (long long)t * TS;
        __syncthreads();                            // prior epilogue readers done
        if (tid < TS) {
            if (is64) {
                rows_s[tid] = (int)ei64[e0 + tid];
                cols_s[tid] = (int)ei64[N_EDGES + e0 + tid];
            } else {
                rows_s[tid] = ei32[e0 + tid];
                cols_s[tid] = ei32[N_EDGES + e0 + tid];
            }
        }
        // Convert this tile's edge_attr -> Ahi/Alo [r][k]
        {
            int r = tid >> 1, k0 = (tid & 1) * 64;
            const float* src = edge_attr + (e0 + r) * HDIM + k0;
#pragma unroll
            for (int kk = 0; kk < 64; kk += 2) {
                uint32_t lo, hi = pack_bf2(src[kk], src[kk + 1], lo);
                *(uint32_t*)&Ahi[r * BPAD + k0 + kk] = hi;
                *(uint32_t*)&Alo[r * BPAD + k0 + kk] = lo;
            }
        }
        __syncthreads();

        float C[2][8][4];
#pragma unroll
        for (int mi = 0; mi < 2; ++mi)
#pragma unroll
            for (int ni = 0; ni < 8; ++ni)
#pragma unroll
                for (int q = 0; q < 4; ++q) C[mi][ni][q] = 0.f;

        for (int pass = 0; pass < 3; ++pass) {
            const __nv_bfloat16* Ap = (pass == 2) ? Alo : Ahi;
            const __nv_bfloat16* Wp = (pass == 1) ? Wlo : Whi;
            for (int ks = 0; ks < 8; ++ks) {
                const int k0 = ks * 16;
                uint32_t a[2][4];
#pragma unroll
                for (int mi = 0; mi < 2; ++mi) {
                    const int rb = m0 + mi * 16;
                    a[mi][0] = *(const uint32_t*)&Ap[(rb + g)     * BPAD + k0 + tg * 2];
                    a[mi][1] = *(const uint32_t*)&Ap[(rb + 8 + g) * BPAD + k0 + tg * 2];
                    a[mi][2] = *(const uint32_t*)&Ap[(rb + g)     * BPAD + k0 + 8 + tg * 2];
                    a[mi][3] = *(const uint32_t*)&Ap[(rb + 8 + g) * BPAD + k0 + 8 + tg * 2];
                }
#pragma unroll
                for (int ni = 0; ni < 8; ++ni) {
                    const int nrow = nb + ni * 8 + g;
                    uint32_t b0 = *(const uint32_t*)&Wp[nrow * BPAD + k0 + tg * 2];
                    uint32_t b1 = *(const uint32_t*)&Wp[nrow * BPAD + k0 + 8 + tg * 2];
                    mma16816(C[0][ni], a[0], b0, b1);
                    mma16816(C[1][ni], a[1], b0, b1);
                }
            }
        }

        // Epilogue: per owned row, gather P, add, relu, scatter-add
#pragma unroll
        for (int mi = 0; mi < 2; ++mi) {
#pragma unroll
            for (int half = 0; half < 2; ++half) {
                const int row = m0 + mi * 16 + half * 8 + g;
                const int rr = rows_s[row], cc = cols_s[row];
                const float* Pr = g_P + (size_t)rr * 256;        // Pa (has b1)
                const float* Pc = g_P + (size_t)cc * 256 + 128;  // Pb
                float* dst = g_Hagg + (size_t)cc * HDIM;
#pragma unroll
                for (int ni = 0; ni < 8; ++ni) {
                    const int col = nb + ni * 8 + tg * 2;
                    float2 pa = *(const float2*)(Pr + col);
                    float2 pb = *(const float2*)(Pc + col);
                    float h0 = fmaxf(C[mi][ni][half * 2 + 0] + pa.x + pb.x, 0.f);
                    float h1 = fmaxf(C[mi][ni][half * 2 + 1] + pa.y + pb.y, 0.f);
                    red2(dst + col, h0, h1);
                }
                if (tg == 0 && nb == 0) red1(g_deg + cc, 1.0f);
            }
        }
    }
}

// agg = Hagg@We2 + deg*b2 ; out = relu([x|agg]@Wn1 + bn1)@Wn2 + bn2
__global__ __launch_bounds__(256) void k_node(const float* __restrict__ x,
                                              const float* __restrict__ We2,
                                              const float* __restrict__ be2,
                                              const float* __restrict__ Wn1,
                                              const float* __restrict__ bn1,
                                              const float* __restrict__ Wn2,
                                              const float* __restrict__ bn2,
                                              float* __restrict__ out) {
    extern __shared__ float smem[];
    float* As  = smem;
    float* As2 = smem + AS_FLOATS;
    float* Bs  = smem + 2 * AS_FLOATS;
    __shared__ float degs[64];
    const int tid = threadIdx.x, tx = tid & 15, ty = tid >> 4;
    const int c0 = tx * 8, r0 = ty * 4;
    const int n0 = blockIdx.x * 64;
    const int nrows = min(64, N_NODES - n0);

    load_A(As, g_Hagg + (size_t)n0 * HDIM, nrows, tid);
    load_B(Bs, We2, tid);
    if (tid < 64) degs[tid] = (n0 + tid < N_NODES) ? g_deg[n0 + tid] : 0.f;
    __syncthreads();
    float acc[4][8]; zero_acc(acc);
    gemm_tile(As, Bs, acc, tx, ty);
    {
        float4 b0 = *(const float4*)(be2 + c0);
        float4 b1 = *(const float4*)(be2 + c0 + 4);
#pragma unroll
        for (int i = 0; i < 4; ++i) {
            float d = degs[r0 + i];
            float* dst = As2 + (r0 + i) * PAD + c0;
            *(float4*)dst       = make_float4(acc[i][0]+d*b0.x, acc[i][1]+d*b0.y, acc[i][2]+d*b0.z, acc[i][3]+d*b0.w);
            *(float4*)(dst + 4) = make_float4(acc[i][4]+d*b1.x, acc[i][5]+d*b1.y, acc[i][6]+d*b1.z, acc[i][7]+d*b1.w);
        }
    }
    __syncthreads();
    load_A(As, x + (size_t)n0 * HDIM, nrows, tid);
    load_B(Bs, Wn1, tid);
    __syncthreads();
    zero_acc(acc);
    gemm_tile(As, Bs, acc, tx, ty);
    __syncthreads();
    load_B(Bs, Wn1 + 128 * HDIM, tid);
    __syncthreads();
    gemm_tile(As2, Bs, acc, tx, ty);
    {
        float4 b0 = *(const float4*)(bn1 + c0);
        float4 b1 = *(const float4*)(bn1 + c0 + 4);
#pragma unroll
        for (int i = 0; i < 4; ++i) {
            float* dst = As + (r0 + i) * PAD + c0;
            *(float4*)dst       = make_float4(fmaxf(acc[i][0]+b0.x,0.f), fmaxf(acc[i][1]+b0.y,0.f),
                                              fmaxf(acc[i][2]+b0.z,0.f), fmaxf(acc[i][3]+b0.w,0.f));
            *(float4*)(dst + 4) = make_float4(fmaxf(acc[i][4]+b1.x,0.f), fmaxf(acc[i][5]+b1.y,0.f),
                                              fmaxf(acc[i][6]+b1.z,0.f), fmaxf(acc[i][7]+b1.w,0.f));
        }
    }
    __syncthreads();
    load_B(Bs, Wn2, tid);
    __syncthreads();
    zero_acc(acc);
    gemm_tile(As, Bs, acc, tx, ty);
    {
        float4 b0 = *(const float4*)(bn2 + c0);
        float4 b1 = *(const float4*)(bn2 + c0 + 4);
#pragma unroll
        for (int i = 0; i < 4; ++i) {
            int r = r0 + i;
            if (r < nrows) {
                float* dst = out + (size_t)(n0 + r) * HDIM + c0;
                *(float4*)dst       = make_float4(acc[i][0]+b0.x, acc[i][1]+b0.y, acc[i][2]+b0.z, acc[i][3]+b0.w);
                *(float4*)(dst + 4) = make_float4(acc[i][4]+b1.x, acc[i][5]+b1.y, acc[i][6]+b1.z, acc[i][7]+b1.w);
            }
        }
    }
}

// ---------------------------------------------------------------------------
extern "C" void kernel_launch(void* const* d_in, const int* in_sizes, int n_in,
                              void* d_out, int out_size) {
    const float* x          = (const float*)d_in[0];
    const void*  edge_index = d_in[1];
    const float* edge_attr  = (const float*)d_in[2];
    const float* We1        = (const float*)d_in[3];
    const float* be1        = (const float*)d_in[4];
    const float* We2        = (const float*)d_in[5];
    const float* be2        = (const float*)d_in[6];
    const float* Wn1        = (const float*)d_in[7];
    const float* bn1        = (const float*)d_in[8];
    const float* Wn2        = (const float*)d_in[9];
    const float* bn2        = (const float*)d_in[10];
    float* out = (float*)d_out;

    cudaFuncSetAttribute(k_node_proj, cudaFuncAttributeMaxDynamicSharedMemorySize, SMEM_PROJ);
    cudaFuncSetAttribute(k_edge_hmma, cudaFuncAttributeMaxDynamicSharedMemorySize, SMEM_EDGE_DYN);
    cudaFuncSetAttribute(k_node,      cudaFuncAttributeMaxDynamicSharedMemorySize, SMEM_NODE);

    const int NB_NODE = (N_NODES + 63) / 64;    // 782
    k_detect<<<1, 32>>>((const long long*)edge_index);
    k_zero<<<256, 256>>>();
    k_node_proj<<<NB_NODE, 256, SMEM_PROJ>>>(x, We1, be1);
    k_edge_hmma<<<148, 256, SMEM_EDGE_DYN>>>(edge_attr, edge_index, We1);
    k_node<<<NB_NODE, 256, SMEM_NODE>>>(x, We2, be2, Wn1, bn1, Wn2, bn2, out);
}

// round 10
// speedup vs baseline: 1.2635x; 1.2635x over previous
#include <cuda_runtime.h>
#include <cuda_bf16.h>
#include <cstdint>

#define N_NODES 50000
#define N_EDGES 800000
#define HDIM    128
#define PAD     132
#define AS_FLOATS (64 * PAD)
#define BS_FLOATS (HDIM * HDIM)
#define SMEM_PROJ ((AS_FLOATS + BS_FLOATS) * 4)
#define SMEM_NODE ((2 * AS_FLOATS + BS_FLOATS) * 4)

// edge-HMMA tile config: 64 edges x 128 cols, bf16 hi/lo split in smem
#define TS   64
#define BPAD 136                                   // bf16 row stride
#define A_EL (TS * BPAD)                           // 8704 elements per A tile
#define W_EL (128 * BPAD)                          // 17408 elements per W tile
#define SMEM_EDGE_DYN ((2 * A_EL + 2 * W_EL) * 2)  // Ahi|Alo|Whi|Wlo = 104448 B (2 CTAs/SM)

// Scratch (device globals — no allocation allowed)
__device__ __align__(16) float g_P[N_NODES * 256];     // [Pa(+b1) | Pb] per node
__device__ __align__(16) float g_Hagg[N_NODES * HDIM]; // segment_sum of relu'd hidden
__device__ __align__(16) float g_deg[N_NODES];         // in-degree (float)
__device__ int g_idx_is64;                             // edge_index dtype flag

// ---------------------------------------------------------------------------
__device__ __forceinline__ void red2(float* p, float a, float b) {
    asm volatile("red.global.add.v2.f32 [%0], {%1,%2};"
                 :: "l"(p), "f"(a), "f"(b) : "memory");
}
__device__ __forceinline__ void red1(float* p, float v) {
    asm volatile("red.global.add.f32 [%0], %1;" :: "l"(p), "f"(v) : "memory");
}

// m16n8k16 row.col bf16 -> f32 accumulate
__device__ __forceinline__ void mma16816(float c[4], const uint32_t a[4],
                                         uint32_t b0, uint32_t b1) {
    asm volatile(
        "mma.sync.aligned.m16n8k16.row.col.f32.bf16.bf16.f32 "
        "{%0,%1,%2,%3}, {%4,%5,%6,%7}, {%8,%9}, {%0,%1,%2,%3};"
        : "+f"(c[0]), "+f"(c[1]), "+f"(c[2]), "+f"(c[3])
        : "r"(a[0]), "r"(a[1]), "r"(a[2]), "r"(a[3]), "r"(b0), "r"(b1));
}

__device__ __forceinline__ uint32_t pack_bf2(float v0, float v1, uint32_t& lo) {
    __nv_bfloat16 h0 = __float2bfloat16_rn(v0);
    __nv_bfloat16 h1 = __float2bfloat16_rn(v1);
    __nv_bfloat16 l0 = __float2bfloat16_rn(v0 - __bfloat162float(h0));
    __nv_bfloat16 l1 = __float2bfloat16_rn(v1 - __bfloat162float(h1));
    lo = (uint32_t)__bfloat16_as_ushort(l0) | ((uint32_t)__bfloat16_as_ushort(l1) << 16);
    return (uint32_t)__bfloat16_as_ushort(h0) | ((uint32_t)__bfloat16_as_ushort(h1) << 16);
}

// ---------------------------------------------------------------------------
// SIMT GEMM helpers (node kernels)
__device__ __forceinline__ void load_A(float* As, const float* __restrict__ src,
                                       int nrows, int tid) {
#pragma unroll
    for (int t = 0; t < 8; ++t) {
        int g  = tid + t * 256;
        int r  = g >> 5;
        int c4 = g & 31;
        float4 v = make_float4(0.f, 0.f, 0.f, 0.f);
        if (r < nrows) v = *(const float4*)(src + r * HDIM + c4 * 4);
        *(float4*)(As + r * PAD + c4 * 4) = v;
    }
}
__device__ __forceinline__ void load_B(float* Bs, const float* __restrict__ B, int tid) {
    const float4* s = (const float4*)B;
    float4* d = (float4*)Bs;
#pragma unroll
    for (int t = 0; t < 16; ++t) d[tid + t * 256] = s[tid + t * 256];
}
__device__ __forceinline__ void gemm_tile(const float* __restrict__ As,
                                          const float* __restrict__ Bs,
                                          float acc[4][8], int tx, int ty) {
    const int r0 = ty * 4, c0 = tx * 8;
#pragma unroll 2
    for (int kk = 0; kk < HDIM; kk += 4) {
        float a[4][4];
#pragma unroll
        for (int i = 0; i < 4; ++i)
            *(float4*)a[i] = *(const float4*)(As + (r0 + i) * PAD + kk);
#pragma unroll
        for (int u = 0; u < 4; ++u) {
            float b[8];
            *(float4*)&b[0] = *(const float4*)(Bs + (kk + u) * HDIM + c0);
            *(float4*)&b[4] = *(const float4*)(Bs + (kk + u) * HDIM + c0 + 4);
#pragma unroll
            for (int i = 0; i < 4; ++i)
#pragma unroll
                for (int j = 0; j < 8; ++j)
                    acc[i][j] = fmaf(a[i][u], b[j], acc[i][j]);
        }
    }
}
__device__ __forceinline__ void zero_acc(float acc[4][8]) {
#pragma unroll
    for (int i = 0; i < 4; ++i)
#pragma unroll
        for (int j = 0; j < 8; ++j) acc[i][j] = 0.f;
}

// ---------------------------------------------------------------------------
__global__ void k_detect(const long long* __restrict__ ei) {
    if (threadIdx.x == 0 && blockIdx.x == 0) {
        int ok = 1;
        for (int i = 0; i < 64; ++i) {
            long long v = ei[i];
            if (v < 0 || v >= N_NODES) { ok = 0; break; }
        }
        g_idx_is64 = ok;
    }
}

__global__ void k_zero() {
    int idx = blockIdx.x * blockDim.x + threadIdx.x;
    float4* p = (float4*)g_Hagg;
    const int n4 = N_NODES * HDIM / 4;
    for (int i = idx; i < n4; i += 256 * 256) p[i] = make_float4(0.f, 0.f, 0.f, 0.f);
    for (int i = idx; i < N_NODES; i += 256 * 256) g_deg[i] = 0.f;
}

// P = [x@W1a + b1 | x@W1b]
__global__ __launch_bounds__(256) void k_node_proj(const float* __restrict__ x,
                                                   const float* __restrict__ We1,
                                                   const float* __restrict__ be1) {
    extern __shared__ float smem[];
    float* As = smem;
    float* Bs = smem + AS_FLOATS;
    const int tid = threadIdx.x, tx = tid & 15, ty = tid >> 4;
    const int c0 = tx * 8, r0 = ty * 4;
    const int n0 = blockIdx.x * 64;
    const int nrows = min(64, N_NODES - n0);

    load_A(As, x + (size_t)n0 * HDIM, nrows, tid);
    load_B(Bs, We1, tid);
    __syncthreads();
    float acc[4][8]; zero_acc(acc);
    gemm_tile(As, Bs, acc, tx, ty);
    float4 b0 = *(const float4*)(be1 + c0);
    float4 b1 = *(const float4*)(be1 + c0 + 4);
#pragma unroll
    for (int i = 0; i < 4; ++i) {
        int r = r0 + i;
        if (r < nrows) {
            float* dst = g_P + (size_t)(n0 + r) * 256 + c0;
            *(float4*)dst       = make_float4(acc[i][0]+b0.x, acc[i][1]+b0.y, acc[i][2]+b0.z, acc[i][3]+b0.w);
            *(float4*)(dst + 4) = make_float4(acc[i][4]+b1.x, acc[i][5]+b1.y, acc[i][6]+b1.z, acc[i][7]+b1.w);
        }
    }
    __syncthreads();
    load_B(Bs, We1 + 128 * HDIM, tid);
    __syncthreads();
    zero_acc(acc);
    gemm_tile(As, Bs, acc, tx, ty);
#pragma unroll
    for (int i = 0; i < 4; ++i) {
        int r = r0 + i;
        if (r < nrows) {
            float* dst = g_P + (size_t)(n0 + r) * 256 + 128 + c0;
            *(float4*)dst       = make_float4(acc[i][0], acc[i][1], acc[i][2], acc[i][3]);
            *(float4*)(dst + 4) = make_float4(acc[i][4], acc[i][5], acc[i][6], acc[i][7]);
        }
    }
}

// ---------------------------------------------------------------------------
// HMMA edge kernel v2: 64-edge tiles, 2 CTAs/SM, coalesced float4 conversion.
// 8 warps as 2(m) x 4(n): warp owns 32 edges x 32 cols. C[2][4][4] = 32 regs.
__global__ __launch_bounds__(256, 2) void k_edge_hmma(const float* __restrict__ edge_attr,
                                                      const void* __restrict__ edge_index,
                                                      const float* __restrict__ We1) {
    extern __shared__ __nv_bfloat16 sm[];
    __shared__ int rows_s[TS];
    __shared__ int cols_s[TS];

    const int tid = threadIdx.x, wid = tid >> 5, lane = tid & 31;
    const int g = lane >> 2, tg = lane & 3;
    __nv_bfloat16* Ahi = sm;
    __nv_bfloat16* Alo = sm + A_EL;
    __nv_bfloat16* Whi = sm + 2 * A_EL;
    __nv_bfloat16* Wlo = sm + 2 * A_EL + W_EL;

    // Convert W1c^T -> Whi/Wlo [n][k] (once per CTA)
    {
        const float* W = We1 + 256 * HDIM;          // W1c rows of We1
        int n = tid >> 1, k0 = (tid & 1) * 64;
        for (int kk = 0; kk < 64; kk += 2) {
            float v0 = W[(k0 + kk) * HDIM + n];
            float v1 = W[(k0 + kk + 1) * HDIM + n];
            uint32_t lo, hi = pack_bf2(v0, v1, lo);
            *(uint32_t*)&Whi[n * BPAD + k0 + kk] = hi;
            *(uint32_t*)&Wlo[n * BPAD + k0 + kk] = lo;
        }
    }

    const int is64 = g_idx_is64;
    const long long* ei64 = (const long long*)edge_index;
    const int*       ei32 = (const int*)edge_index;

    const int m0 = (wid & 1) * 32;                  // 2 m-warps: edge rows
    const int nb = (wid >> 1) * 32;                 // 4 n-warps: cols
    const int ntiles = N_EDGES / TS;                // 12500, no tail

    // conversion mapping: thread -> (row, 32-col quarter), coalesced float4
    const int cr = tid >> 2, ck = (tid & 3) * 32;

    for (int t = blockIdx.x; t < ntiles; t += gridDim.x) {
        const long long e0 = (long long)t * TS;
        __syncthreads();                            // prior tile's readers done
        if (tid < TS) {
            if (is64) {
                rows_s[tid] = (int)ei64[e0 + tid];
                cols_s[tid] = (int)ei64[N_EDGES + e0 + tid];
            } else {
                rows_s[tid] = ei32[e0 + tid];
                cols_s[tid] = ei32[N_EDGES + e0 + tid];
            }
        }
        // Convert this tile's edge_attr -> Ahi/Alo, fully-coalesced float4 loads
        {
            const float4* src = (const float4*)(edge_attr + (e0 + cr) * HDIM + ck);
#pragma unroll
            for (int q = 0; q < 8; ++q) {
                float4 v = src[q];
                uint32_t lo0, hi0 = pack_bf2(v.x, v.y, lo0);
                uint32_t lo1, hi1 = pack_bf2(v.z, v.w, lo1);
                uint32_t off = cr * BPAD + ck + q * 4;
                *(uint2*)&Ahi[off] = make_uint2(hi0, hi1);
                *(uint2*)&Alo[off] = make_uint2(lo0, lo1);
            }
        }
        __syncthreads();

        float C[2][4][4];
#pragma unroll
        for (int mi = 0; mi < 2; ++mi)
#pragma unroll
            for (int ni = 0; ni < 4; ++ni)
#pragma unroll
                for (int q = 0; q < 4; ++q) C[mi][ni][q] = 0.f;

#pragma unroll
        for (int pass = 0; pass < 3; ++pass) {
            const __nv_bfloat16* Ap = (pass == 2) ? Alo : Ahi;
            const __nv_bfloat16* Wp = (pass == 1) ? Wlo : Whi;
#pragma unroll
            for (int ks = 0; ks < 8; ++ks) {
                const int k0 = ks * 16;
                uint32_t a[2][4];
#pragma unroll
                for (int mi = 0; mi < 2; ++mi) {
                    const int rb = m0 + mi * 16;
                    a[mi][0] = *(const uint32_t*)&Ap[(rb + g)     * BPAD + k0 + tg * 2];
                    a[mi][1] = *(const uint32_t*)&Ap[(rb + 8 + g) * BPAD + k0 + tg * 2];
                    a[mi][2] = *(const uint32_t*)&Ap[(rb + g)     * BPAD + k0 + 8 + tg * 2];
                    a[mi][3] = *(const uint32_t*)&Ap[(rb + 8 + g) * BPAD + k0 + 8 + tg * 2];
                }
#pragma unroll
                for (int ni = 0; ni < 4; ++ni) {
                    const int nrow = nb + ni * 8 + g;
                    uint32_t b0 = *(const uint32_t*)&Wp[nrow * BPAD + k0 + tg * 2];
                    uint32_t b1 = *(const uint32_t*)&Wp[nrow * BPAD + k0 + 8 + tg * 2];
                    mma16816(C[0][ni], a[0], b0, b1);
                    mma16816(C[1][ni], a[1], b0, b1);
                }
            }
        }

        // Epilogue: per owned row, gather P, add, relu, scatter-add
#pragma unroll
        for (int mi = 0; mi < 2; ++mi) {
#pragma unroll
            for (int half = 0; half < 2; ++half) {
                const int row = m0 + mi * 16 + half * 8 + g;
                const int rr = rows_s[row], cc = cols_s[row];
                const float* Pr = g_P + (size_t)rr * 256;        // Pa (has b1)
                const float* Pc = g_P + (size_t)cc * 256 + 128;  // Pb
                float* dst = g_Hagg + (size_t)cc * HDIM;
#pragma unroll
                for (int ni = 0; ni < 4; ++ni) {
                    const int col = nb + ni * 8 + tg * 2;
                    float2 pa = *(const float2*)(Pr + col);
                    float2 pb = *(const float2*)(Pc + col);
                    float h0 = fmaxf(C[mi][ni][half * 2 + 0] + pa.x + pb.x, 0.f);
                    float h1 = fmaxf(C[mi][ni][half * 2 + 1] + pa.y + pb.y, 0.f);
                    red2(dst + col, h0, h1);
                }
                if (tg == 0 && nb == 0) red1(g_deg + cc, 1.0f);
            }
        }
    }
}

// agg = Hagg@We2 + deg*b2 ; out = relu([x|agg]@Wn1 + bn1)@Wn2 + bn2
__global__ __launch_bounds__(256) void k_node(const float* __restrict__ x,
                                              const float* __restrict__ We2,
                                              const float* __restrict__ be2,
                                              const float* __restrict__ Wn1,
                                              const float* __restrict__ bn1,
                                              const float* __restrict__ Wn2,
                                              const float* __restrict__ bn2,
                                              float* __restrict__ out) {
    extern __shared__ float smem[];
    float* As  = smem;
    float* As2 = smem + AS_FLOATS;
    float* Bs  = smem + 2 * AS_FLOATS;
    __shared__ float degs[64];
    const int tid = threadIdx.x, tx = tid & 15, ty = tid >> 4;
    const int c0 = tx * 8, r0 = ty * 4;
    const int n0 = blockIdx.x * 64;
    const int nrows = min(64, N_NODES - n0);

    load_A(As, g_Hagg + (size_t)n0 * HDIM, nrows, tid);
    load_B(Bs, We2, tid);
    if (tid < 64) degs[tid] = (n0 + tid < N_NODES) ? g_deg[n0 + tid] : 0.f;
    __syncthreads();
    float acc[4][8]; zero_acc(acc);
    gemm_tile(As, Bs, acc, tx, ty);
    {
        float4 b0 = *(const float4*)(be2 + c0);
        float4 b1 = *(const float4*)(be2 + c0 + 4);
#pragma unroll
        for (int i = 0; i < 4; ++i) {
            float d = degs[r0 + i];
            float* dst = As2 + (r0 + i) * PAD + c0;
            *(float4*)dst       = make_float4(acc[i][0]+d*b0.x, acc[i][1]+d*b0.y, acc[i][2]+d*b0.z, acc[i][3]+d*b0.w);
            *(float4*)(dst + 4) = make_float4(acc[i][4]+d*b1.x, acc[i][5]+d*b1.y, acc[i][6]+d*b1.z, acc[i][7]+d*b1.w);
        }
    }
    __syncthreads();
    load_A(As, x + (size_t)n0 * HDIM, nrows, tid);
    load_B(Bs, Wn1, tid);
    __syncthreads();
    zero_acc(acc);
    gemm_tile(As, Bs, acc, tx, ty);
    __syncthreads();
    load_B(Bs, Wn1 + 128 * HDIM, tid);
    __syncthreads();
    gemm_tile(As2, Bs, acc, tx, ty);
    {
        float4 b0 = *(const float4*)(bn1 + c0);
        float4 b1 = *(const float4*)(bn1 + c0 + 4);
#pragma unroll
        for (int i = 0; i < 4; ++i) {
            float* dst = As + (r0 + i) * PAD + c0;
            *(float4*)dst       = make_float4(fmaxf(acc[i][0]+b0.x,0.f), fmaxf(acc[i][1]+b0.y,0.f),
                                              fmaxf(acc[i][2]+b0.z,0.f), fmaxf(acc[i][3]+b0.w,0.f));
            *(float4*)(dst + 4) = make_float4(fmaxf(acc[i][4]+b1.x,0.f), fmaxf(acc[i][5]+b1.y,0.f),
                                              fmaxf(acc[i][6]+b1.z,0.f), fmaxf(acc[i][7]+b1.w,0.f));
        }
    }
    __syncthreads();
    load_B(Bs, Wn2, tid);
    __syncthreads();
    zero_acc(acc);
    gemm_tile(As, Bs, acc, tx, ty);
    {
        float4 b0 = *(const float4*)(bn2 + c0);
        float4 b1 = *(const float4*)(bn2 + c0 + 4);
#pragma unroll
        for (int i = 0; i < 4; ++i) {
            int r = r0 + i;
            if (r < nrows) {
                float* dst = out + (size_t)(n0 + r) * HDIM + c0;
                *(float4*)dst       = make_float4(acc[i][0]+b0.x, acc[i][1]+b0.y, acc[i][2]+b0.z, acc[i][3]+b0.w);
                *(float4*)(dst + 4) = make_float4(acc[i][4]+b1.x, acc[i][5]+b1.y, acc[i][6]+b1.z, acc[i][7]+b1.w);
            }
        }
    }
}

// ---------------------------------------------------------------------------
extern "C" void kernel_launch(void* const* d_in, const int* in_sizes, int n_in,
                              void* d_out, int out_size) {
    const float* x          = (const float*)d_in[0];
    const void*  edge_index = d_in[1];
    const float* edge_attr  = (const float*)d_in[2];
    const float* We1        = (const float*)d_in[3];
    const float* be1        = (const float*)d_in[4];
    const float* We2        = (const float*)d_in[5];
    const float* be2        = (const float*)d_in[6];
    const float* Wn1        = (const float*)d_in[7];
    const float* bn1        = (const float*)d_in[8];
    const float* Wn2        = (const float*)d_in[9];
    const float* bn2        = (const float*)d_in[10];
    float* out = (float*)d_out;

    cudaFuncSetAttribute(k_node_proj, cudaFuncAttributeMaxDynamicSharedMemorySize, SMEM_PROJ);
    cudaFuncSetAttribute(k_edge_hmma, cudaFuncAttributeMaxDynamicSharedMemorySize, SMEM_EDGE_DYN);
    cudaFuncSetAttribute(k_node,      cudaFuncAttributeMaxDynamicSharedMemorySize, SMEM_NODE);

    const int NB_NODE = (N_NODES + 63) / 64;    // 782
    k_detect<<<1, 32>>>((const long long*)edge_index);
    k_zero<<<256, 256>>>();
    k_node_proj<<<NB_NODE, 256, SMEM_PROJ>>>(x, We1, be1);
    k_edge_hmma<<<296, 256, SMEM_EDGE_DYN>>>(edge_attr, edge_index, We1);
    k_node<<<NB_NODE, 256, SMEM_NODE>>>(x, We2, be2, Wn1, bn1, Wn2, bn2, out);
}